// round 1
// baseline (speedup 1.0000x reference)
#include <cuda_runtime.h>
#include <math.h>

// ---------------------------------------------------------------------------
// Problem constants
// ---------------------------------------------------------------------------
constexpr int BATCH = 16;
constexpr int HH    = 56;
constexpr int WWID  = 56;
constexpr int CDIM  = 384;
constexpr int NHEAD = 12;
constexpr int HDIM  = 32;
constexpr int WSZ   = 7;
constexpr int SHIFT = 3;
constexpr int NTOK  = 49;                 // tokens per window
constexpr int NWIN  = BATCH * 64;         // 1024 windows
constexpr int TOK   = NWIN * NTOK;        // 50176 tokens
constexpr float ATT_SCALE = 0.17677669529663687f;   // 32^-0.5
constexpr float LN_EPS    = 1e-3f;

// ---------------------------------------------------------------------------
// Scratch (device globals: no allocation allowed in kernel_launch)
// ---------------------------------------------------------------------------
__device__ float g_wins[TOK * CDIM];          // LN1 + shift-gathered windows
__device__ float g_qkv [TOK * 3 * CDIM];      // qkv projection
__device__ float g_att [TOK * CDIM];          // attention output (pre-proj)
__device__ float g_x1  [TOK * CDIM];          // post-attention residual
__device__ float g_ln2 [TOK * CDIM];          // LN2 output
__device__ float g_h   [TOK * 4 * CDIM];      // MLP hidden

// ---------------------------------------------------------------------------
// LayerNorm (one block per token, 384 threads).
// gather=1: token index is (window, n) and we read x at the cyclically
// shifted source location (fused roll + window_partition).
// ---------------------------------------------------------------------------
__global__ void __launch_bounds__(384)
ln_kernel(const float* __restrict__ X, const float* __restrict__ gam,
          const float* __restrict__ bet, float* __restrict__ Y, int gather)
{
    int tok = blockIdx.x;
    int src = tok;
    if (gather) {
        int win = tok / NTOK, n = tok % NTOK;
        int b  = win >> 6, wi = win & 63;
        int wh = wi >> 3,  ww = wi & 7;
        int i  = n / WSZ,  j  = n % WSZ;
        int hs = wh * WSZ + i, ws = ww * WSZ + j;
        int sh = hs + SHIFT; if (sh >= HH)  sh -= HH;     // roll(-3) on H
        int sw = ws - SHIFT; if (sw < 0)    sw += WWID;   // roll(+3) on W
        src = (b * HH + sh) * WWID + sw;
    }
    int c = threadIdx.x;
    float v = X[(size_t)src * CDIM + c];

    float a = v, b2 = v * v;
    #pragma unroll
    for (int off = 16; off; off >>= 1) {
        a  += __shfl_xor_sync(~0u, a,  off);
        b2 += __shfl_xor_sync(~0u, b2, off);
    }
    __shared__ float s1[12], s2[12];
    __shared__ float mu_s, rs_s;
    int wid = threadIdx.x >> 5, lane = threadIdx.x & 31;
    if (!lane) { s1[wid] = a; s2[wid] = b2; }
    __syncthreads();
    if (threadIdx.x == 0) {
        float sa = 0.f, sb = 0.f;
        #pragma unroll
        for (int k = 0; k < 12; k++) { sa += s1[k]; sb += s2[k]; }
        float mu  = sa / CDIM;
        float var = sb / CDIM - mu * mu;
        mu_s = mu;
        rs_s = rsqrtf(var + LN_EPS);
    }
    __syncthreads();
    Y[(size_t)tok * CDIM + c] = (v - mu_s) * rs_s * gam[c] + bet[c];
}

// ---------------------------------------------------------------------------
// Destination row for the proj epilogue: window_reverse + roll(+3,+3) scatter.
// (Faithful to the reference's asymmetric rolls.)
// ---------------------------------------------------------------------------
__device__ __forceinline__ int dest_row(int tok)
{
    int win = tok / NTOK, n = tok % NTOK;
    int b  = win >> 6, wi = win & 63;
    int wh = wi >> 3,  ww = wi & 7;
    int i  = n / WSZ,  j  = n % WSZ;
    int hs = wh * WSZ + i, ws = ww * WSZ + j;
    int h = hs + SHIFT; if (h >= HH)   h -= HH;
    int w = ws + SHIFT; if (w >= WWID) w -= WWID;
    return (b * HH + h) * WWID + w;
}

// ---------------------------------------------------------------------------
// fp32 tiled GEMM: C = A[MxK] @ B[KxN] + bias, 64x64 tile, BK=16, 256 thr.
// MODE 0: plain+bias   MODE 1: +bias, exact GELU
// MODE 2: +bias, scatter rows via dest_row, add residual res[dest]
// MODE 3: +bias, add residual res[row]
// Requires M%64==0, N%64==0, K%16==0 (true for all calls here).
// ---------------------------------------------------------------------------
template<int MODE>
__global__ void __launch_bounds__(256)
gemm_kernel(const float* __restrict__ A, const float* __restrict__ B,
            const float* __restrict__ bias, const float* __restrict__ res,
            float* __restrict__ C, int M, int N, int K)
{
    __shared__ __align__(16) float As[16][64];
    __shared__ __align__(16) float Bs[16][64];

    int tid = threadIdx.x;
    int bm = blockIdx.y * 64, bn = blockIdx.x * 64;
    int tx = tid & 15, ty = tid >> 4;

    int arow = tid >> 2,  acol = (tid & 3)  * 4;
    int brow = tid >> 4,  bcol = (tid & 15) * 4;

    float acc[4][4] = {};

    for (int kt = 0; kt < K; kt += 16) {
        float4 av = *(const float4*)&A[(size_t)(bm + arow) * K + kt + acol];
        float4 bv = *(const float4*)&B[(size_t)(kt + brow) * N + bn + bcol];
        As[acol + 0][arow] = av.x;
        As[acol + 1][arow] = av.y;
        As[acol + 2][arow] = av.z;
        As[acol + 3][arow] = av.w;
        *(float4*)&Bs[brow][bcol] = bv;
        __syncthreads();
        #pragma unroll
        for (int k = 0; k < 16; k++) {
            float4 a = *(const float4*)&As[k][ty * 4];
            float4 b = *(const float4*)&Bs[k][tx * 4];
            float ar[4] = {a.x, a.y, a.z, a.w};
            float br[4] = {b.x, b.y, b.z, b.w};
            #pragma unroll
            for (int i = 0; i < 4; i++)
                #pragma unroll
                for (int j = 0; j < 4; j++)
                    acc[i][j] = fmaf(ar[i], br[j], acc[i][j]);
        }
        __syncthreads();
    }

    #pragma unroll
    for (int i = 0; i < 4; i++) {
        int r  = bm + ty * 4 + i;
        int dr = (MODE == 2) ? dest_row(r) : r;
        #pragma unroll
        for (int j = 0; j < 4; j++) {
            int col = bn + tx * 4 + j;
            float v = acc[i][j] + bias[col];
            if (MODE == 1) v = 0.5f * v * (1.0f + erff(v * 0.70710678118654752f));
            if (MODE == 2) v += res[(size_t)dr * N + col];
            if (MODE == 3) v += res[(size_t)r  * N + col];
            C[(size_t)dr * N + col] = v;
        }
    }
}

// ---------------------------------------------------------------------------
// Attention: one CTA per (window, head). S = q k^T + rel-pos bias + shift
// mask (computed analytically from region ids), softmax, P @ V.
// ---------------------------------------------------------------------------
__global__ void __launch_bounds__(256)
attn_kernel(const float* __restrict__ qkv, const float* __restrict__ relt,
            float* __restrict__ outp)
{
    int blk  = blockIdx.x;
    int win  = blk / NHEAD;
    int head = blk % NHEAD;

    __shared__ float q [49][32];
    __shared__ float kk[49][32];
    __shared__ float vv[49][32];
    __shared__ float S [49][56];
    __shared__ int   cnt[49];

    int tid = threadIdx.x;

    for (int idx = tid; idx < 49 * 32; idx += 256) {
        int n = idx >> 5, d = idx & 31;
        size_t base = (size_t)(win * 49 + n) * 1152 + head * 32 + d;
        q [n][d] = qkv[base]       * ATT_SCALE;
        kk[n][d] = qkv[base + 384];
        vv[n][d] = qkv[base + 768];
    }
    if (tid < 49) {
        int wi = win & 63;
        int wh = wi >> 3, ww = wi & 7;
        int i = tid / 7, j = tid % 7;
        int h = wh * 7 + i, w = ww * 7 + j;
        int rh = (h < HH - WSZ)   ? 0 : (h < HH - SHIFT   ? 1 : 2);
        int rw = (w < WWID - WSZ) ? 0 : (w < WWID - SHIFT ? 1 : 2);
        cnt[tid] = rh * 3 + rw;
    }
    __syncthreads();

    for (int p = tid; p < 49 * 49; p += 256) {
        int n = p / 49, m = p % 49;
        float acc = 0.f;
        #pragma unroll
        for (int d = 0; d < 32; d++) acc = fmaf(q[n][d], kk[m][d], acc);
        int di = n / 7 - m / 7 + 6;
        int dj = n % 7 - m % 7 + 6;
        float bias = relt[(di * 13 + dj) * NHEAD + head];
        float mask = (cnt[n] != cnt[m]) ? -100.f : 0.f;
        S[n][m] = acc + bias + mask;
    }
    __syncthreads();

    int wid = tid >> 5, lane = tid & 31;
    for (int n = wid; n < 49; n += 8) {
        float v0 = S[n][lane];
        float v1 = (lane < 17) ? S[n][lane + 32] : -1e30f;
        float mx = fmaxf(v0, v1);
        #pragma unroll
        for (int off = 16; off; off >>= 1)
            mx = fmaxf(mx, __shfl_xor_sync(~0u, mx, off));
        float e0 = expf(v0 - mx);
        float e1 = (lane < 17) ? expf(v1 - mx) : 0.f;
        float sm = e0 + e1;
        #pragma unroll
        for (int off = 16; off; off >>= 1)
            sm += __shfl_xor_sync(~0u, sm, off);
        float inv = 1.f / sm;
        S[n][lane] = e0 * inv;
        if (lane < 17) S[n][lane + 32] = e1 * inv;
    }
    __syncthreads();

    for (int idx = tid; idx < 49 * 32; idx += 256) {
        int n = idx >> 5, d = idx & 31;
        float acc = 0.f;
        #pragma unroll
        for (int m = 0; m < 49; m++) acc = fmaf(S[n][m], vv[m][d], acc);
        outp[(size_t)(win * 49 + n) * 384 + head * 32 + d] = acc;
    }
}

// ---------------------------------------------------------------------------
// Launch
// ---------------------------------------------------------------------------
extern "C" void kernel_launch(void* const* d_in, const int* in_sizes, int n_in,
                              void* d_out, int out_size)
{
    const float* x      = (const float*)d_in[0];
    const float* ln1_g  = (const float*)d_in[1];
    const float* ln1_b  = (const float*)d_in[2];
    const float* ln2_g  = (const float*)d_in[3];
    const float* ln2_b  = (const float*)d_in[4];
    const float* qkv_w  = (const float*)d_in[5];
    const float* qkv_b  = (const float*)d_in[6];
    const float* proj_w = (const float*)d_in[7];
    const float* proj_b = (const float*)d_in[8];
    const float* mlp_w1 = (const float*)d_in[9];
    const float* mlp_b1 = (const float*)d_in[10];
    const float* mlp_w2 = (const float*)d_in[11];
    const float* mlp_b2 = (const float*)d_in[12];
    const float* relt   = (const float*)d_in[13];
    float* out = (float*)d_out;

    float *wins, *qkvb, *att, *x1, *ln2o, *hbuf;
    cudaGetSymbolAddress((void**)&wins, g_wins);
    cudaGetSymbolAddress((void**)&qkvb, g_qkv);
    cudaGetSymbolAddress((void**)&att,  g_att);
    cudaGetSymbolAddress((void**)&x1,   g_x1);
    cudaGetSymbolAddress((void**)&ln2o, g_ln2);
    cudaGetSymbolAddress((void**)&hbuf, g_h);

    // 1. LN1 + cyclic shift + window partition
    ln_kernel<<<TOK, 384>>>(x, ln1_g, ln1_b, wins, 1);

    // 2. QKV GEMM: [50176,384] @ [384,1152]
    gemm_kernel<0><<<dim3(1152 / 64, TOK / 64), 256>>>(
        wins, qkv_w, qkv_b, nullptr, qkvb, TOK, 1152, 384);

    // 3. Windowed attention
    attn_kernel<<<NWIN * NHEAD, 256>>>(qkvb, relt, att);

    // 4. Proj GEMM + window reverse + reverse roll + residual
    gemm_kernel<2><<<dim3(384 / 64, TOK / 64), 256>>>(
        att, proj_w, proj_b, x, x1, TOK, 384, 384);

    // 5. LN2
    ln_kernel<<<TOK, 384>>>(x1, ln2_g, ln2_b, ln2o, 0);

    // 6. MLP1 + exact GELU: [50176,384] @ [384,1536]
    gemm_kernel<1><<<dim3(1536 / 64, TOK / 64), 256>>>(
        ln2o, mlp_w1, mlp_b1, nullptr, hbuf, TOK, 1536, 384);

    // 7. MLP2 + residual: [50176,1536] @ [1536,384] -> d_out
    gemm_kernel<3><<<dim3(384 / 64, TOK / 64), 256>>>(
        hbuf, mlp_w2, mlp_b2, x1, out, TOK, 384, 1536);
}

// round 2
// speedup vs baseline: 1.1630x; 1.1630x over previous
#include <cuda_runtime.h>
#include <math.h>

// ---------------------------------------------------------------------------
// Problem constants
// ---------------------------------------------------------------------------
constexpr int BATCH = 16;
constexpr int HH    = 56;
constexpr int WWID  = 56;
constexpr int CDIM  = 384;
constexpr int NHEAD = 12;
constexpr int WSZ   = 7;
constexpr int SHIFT = 3;
constexpr int NTOK  = 49;
constexpr int NWIN  = BATCH * 64;
constexpr int TOK   = NWIN * NTOK;        // 50176
constexpr float ATT_SCALE = 0.17677669529663687f;
constexpr float LN_EPS    = 1e-3f;

// ---------------------------------------------------------------------------
// Scratch
// ---------------------------------------------------------------------------
__device__ float g_wins[TOK * CDIM];
__device__ float g_qkv [TOK * 3 * CDIM];
__device__ float g_att [TOK * CDIM];
__device__ float g_x1  [TOK * CDIM];
__device__ float g_ln2 [TOK * CDIM];
__device__ float g_h   [TOK * 4 * CDIM];

// ---------------------------------------------------------------------------
// LayerNorm (one block per token). gather=1 fuses roll(-3,+3)+window partition
// ---------------------------------------------------------------------------
__global__ void __launch_bounds__(384)
ln_kernel(const float* __restrict__ X, const float* __restrict__ gam,
          const float* __restrict__ bet, float* __restrict__ Y, int gather)
{
    int tok = blockIdx.x;
    int src = tok;
    if (gather) {
        int win = tok / NTOK, n = tok % NTOK;
        int b  = win >> 6, wi = win & 63;
        int wh = wi >> 3,  ww = wi & 7;
        int i  = n / WSZ,  j  = n % WSZ;
        int hs = wh * WSZ + i, ws = ww * WSZ + j;
        int sh = hs + SHIFT; if (sh >= HH)  sh -= HH;
        int sw = ws - SHIFT; if (sw < 0)    sw += WWID;
        src = (b * HH + sh) * WWID + sw;
    }
    int c = threadIdx.x;
    float v = X[(size_t)src * CDIM + c];

    float a = v, b2 = v * v;
    #pragma unroll
    for (int off = 16; off; off >>= 1) {
        a  += __shfl_xor_sync(~0u, a,  off);
        b2 += __shfl_xor_sync(~0u, b2, off);
    }
    __shared__ float s1[12], s2[12];
    __shared__ float mu_s, rs_s;
    int wid = threadIdx.x >> 5, lane = threadIdx.x & 31;
    if (!lane) { s1[wid] = a; s2[wid] = b2; }
    __syncthreads();
    if (threadIdx.x == 0) {
        float sa = 0.f, sb = 0.f;
        #pragma unroll
        for (int k = 0; k < 12; k++) { sa += s1[k]; sb += s2[k]; }
        float mu  = sa / CDIM;
        float var = sb / CDIM - mu * mu;
        mu_s = mu;
        rs_s = rsqrtf(var + LN_EPS);
    }
    __syncthreads();
    Y[(size_t)tok * CDIM + c] = (v - mu_s) * rs_s * gam[c] + bet[c];
}

__device__ __forceinline__ int dest_row(int tok)
{
    int win = tok / NTOK, n = tok % NTOK;
    int b  = win >> 6, wi = win & 63;
    int wh = wi >> 3,  ww = wi & 7;
    int i  = n / WSZ,  j  = n % WSZ;
    int hs = wh * WSZ + i, ws = ww * WSZ + j;
    int h = hs + SHIFT; if (h >= HH)   h -= HH;
    int w = ws + SHIFT; if (w >= WWID) w -= WWID;
    return (b * HH + h) * WWID + w;
}

// ---------------------------------------------------------------------------
// tf32 tensor-core GEMM. 128x128 CTA tile, BK=16, 8 warps (64x32 warp tile),
// mma.sync.m16n8k8.tf32 with fp32 accumulation.
// Fragment-swizzled SMEM: A frags read as LDS.128, B frags as LDS.64.
// MODE 0: +bias  MODE 1: +bias,GELU  MODE 2: +bias,scatter+res  MODE 3: +bias,+res
// Requires M%128==0, N%128==0, K%16==0.
// ---------------------------------------------------------------------------
__device__ __forceinline__ unsigned f2tf(float v)
{
    unsigned r;
    asm("cvt.rna.tf32.f32 %0, %1;" : "=r"(r) : "f"(v));
    return r;
}

__device__ __forceinline__ void mma_tf32(float* c, const unsigned* a, const unsigned* b)
{
    asm volatile(
        "mma.sync.aligned.m16n8k8.row.col.f32.tf32.tf32.f32 "
        "{%0,%1,%2,%3}, {%4,%5,%6,%7}, {%8,%9}, {%0,%1,%2,%3};"
        : "+f"(c[0]), "+f"(c[1]), "+f"(c[2]), "+f"(c[3])
        : "r"(a[0]), "r"(a[1]), "r"(a[2]), "r"(a[3]), "r"(b[0]), "r"(b[1]));
}

// A-fragment smem offset: tile r(0..127), c(0..15)
__device__ __forceinline__ int a_off(int r, int c)
{
    int ks = c >> 3, cl = c & 7, mt = r >> 4, rr = r & 15;
    return (((ks * 8 + mt) * 32 + ((rr & 7) << 2) + (cl & 3)) << 2)
           + (rr >> 3) + ((cl >> 2) << 1);
}
// B-fragment smem offset: k(0..15), n(0..127)
__device__ __forceinline__ int b_off(int k, int n)
{
    int ks = k >> 3, kl = k & 7, nt = n >> 3;
    return (((ks * 16 + nt) * 32 + ((n & 7) << 2) + (kl & 3)) << 1) + (kl >> 2);
}

template<int MODE>
__global__ void __launch_bounds__(256)
gemm_tc(const float* __restrict__ A, const float* __restrict__ B,
        const float* __restrict__ bias, const float* __restrict__ res,
        float* __restrict__ C, int M, int N, int K)
{
    __shared__ __align__(16) unsigned As[2][2048];   // 8KB x2
    __shared__ __align__(16) unsigned Bs[2][2048];   // 8KB x2

    const int tid  = threadIdx.x;
    const int bm   = blockIdx.y * 128, bn = blockIdx.x * 128;
    const int warp = tid >> 5, lane = tid & 31;
    const int wm   = warp & 1, wn = warp >> 1;       // 2 x 4 warp grid

    const int ar = tid >> 2;             // A load: rows ar, ar+64
    const int ac = (tid & 3) << 2;       // cols ac..ac+3
    const int br = tid >> 5;             // B load: rows br, br+8
    const int bc = (tid & 31) << 2;      // cols bc..bc+3

    float acc[16][4];
    #pragma unroll
    for (int i = 0; i < 16; i++)
        #pragma unroll
        for (int j = 0; j < 4; j++) acc[i][j] = 0.f;

    float4 a0, a1, b0, b1;
    a0 = *(const float4*)&A[(size_t)(bm + ar)      * K + ac];
    a1 = *(const float4*)&A[(size_t)(bm + ar + 64) * K + ac];
    b0 = *(const float4*)&B[(size_t)(br)     * N + bn + bc];
    b1 = *(const float4*)&B[(size_t)(br + 8) * N + bn + bc];

    // store tile into fragment-swizzled smem (with tf32 rounding)
    #define STORE_TILE(BUF)                                                  \
    {                                                                        \
        unsigned* pa = As[BUF]; unsigned* pb = Bs[BUF];                      \
        pa[a_off(ar,      ac + 0)] = f2tf(a0.x);                             \
        pa[a_off(ar,      ac + 1)] = f2tf(a0.y);                             \
        pa[a_off(ar,      ac + 2)] = f2tf(a0.z);                             \
        pa[a_off(ar,      ac + 3)] = f2tf(a0.w);                             \
        pa[a_off(ar + 64, ac + 0)] = f2tf(a1.x);                             \
        pa[a_off(ar + 64, ac + 1)] = f2tf(a1.y);                             \
        pa[a_off(ar + 64, ac + 2)] = f2tf(a1.z);                             \
        pa[a_off(ar + 64, ac + 3)] = f2tf(a1.w);                             \
        pb[b_off(br,     bc + 0)] = f2tf(b0.x);                              \
        pb[b_off(br,     bc + 1)] = f2tf(b0.y);                              \
        pb[b_off(br,     bc + 2)] = f2tf(b0.z);                              \
        pb[b_off(br,     bc + 3)] = f2tf(b0.w);                              \
        pb[b_off(br + 8, bc + 0)] = f2tf(b1.x);                              \
        pb[b_off(br + 8, bc + 1)] = f2tf(b1.y);                              \
        pb[b_off(br + 8, bc + 2)] = f2tf(b1.z);                              \
        pb[b_off(br + 8, bc + 3)] = f2tf(b1.w);                              \
    }

    STORE_TILE(0)
    int buf = 0;

    for (int kt = 16; ; kt += 16) {
        __syncthreads();
        bool more = kt < K;
        if (more) {
            a0 = *(const float4*)&A[(size_t)(bm + ar)      * K + kt + ac];
            a1 = *(const float4*)&A[(size_t)(bm + ar + 64) * K + kt + ac];
            b0 = *(const float4*)&B[(size_t)(kt + br)     * N + bn + bc];
            b1 = *(const float4*)&B[(size_t)(kt + br + 8) * N + bn + bc];
        }
        #pragma unroll
        for (int ks = 0; ks < 2; ks++) {
            unsigned av[4][4], bv[4][2];
            #pragma unroll
            for (int i = 0; i < 4; i++) {
                uint4 t = *(const uint4*)&As[buf][(((ks * 8) + (wm * 4 + i)) * 32 + lane) * 4];
                av[i][0] = t.x; av[i][1] = t.y; av[i][2] = t.z; av[i][3] = t.w;
            }
            #pragma unroll
            for (int j = 0; j < 4; j++) {
                uint2 t = *(const uint2*)&Bs[buf][(((ks * 16) + (wn * 4 + j)) * 32 + lane) * 2];
                bv[j][0] = t.x; bv[j][1] = t.y;
            }
            #pragma unroll
            for (int i = 0; i < 4; i++)
                #pragma unroll
                for (int j = 0; j < 4; j++)
                    mma_tf32(acc[i * 4 + j], av[i], bv[j]);
        }
        if (!more) break;
        STORE_TILE(buf ^ 1)
        buf ^= 1;
    }
    #undef STORE_TILE

    // ---- epilogue ----
    const int g = lane >> 2, t = lane & 3;
    #pragma unroll
    for (int i = 0; i < 4; i++) {
        int r0 = bm + wm * 64 + i * 16 + g;
        int r1 = r0 + 8;
        int d0 = (MODE == 2) ? dest_row(r0) : r0;
        int d1 = (MODE == 2) ? dest_row(r1) : r1;
        #pragma unroll
        for (int j = 0; j < 4; j++) {
            int col = bn + wn * 32 + j * 8 + t * 2;
            float bc0 = bias[col], bc1 = bias[col + 1];
            float v00 = acc[i * 4 + j][0] + bc0;
            float v01 = acc[i * 4 + j][1] + bc1;
            float v10 = acc[i * 4 + j][2] + bc0;
            float v11 = acc[i * 4 + j][3] + bc1;
            if (MODE == 1) {
                v00 = 0.5f * v00 * (1.0f + erff(v00 * 0.70710678118654752f));
                v01 = 0.5f * v01 * (1.0f + erff(v01 * 0.70710678118654752f));
                v10 = 0.5f * v10 * (1.0f + erff(v10 * 0.70710678118654752f));
                v11 = 0.5f * v11 * (1.0f + erff(v11 * 0.70710678118654752f));
            }
            if (MODE == 2 || MODE == 3) {
                v00 += res[(size_t)d0 * N + col];
                v01 += res[(size_t)d0 * N + col + 1];
                v10 += res[(size_t)d1 * N + col];
                v11 += res[(size_t)d1 * N + col + 1];
            }
            *(float2*)&C[(size_t)d0 * N + col] = make_float2(v00, v01);
            *(float2*)&C[(size_t)d1 * N + col] = make_float2(v10, v11);
        }
    }
}

// ---------------------------------------------------------------------------
// Attention: one CTA per (window, head)
// ---------------------------------------------------------------------------
__global__ void __launch_bounds__(256)
attn_kernel(const float* __restrict__ qkv, const float* __restrict__ relt,
            float* __restrict__ outp)
{
    int blk  = blockIdx.x;
    int win  = blk / NHEAD;
    int head = blk % NHEAD;

    __shared__ float q [49][32];
    __shared__ float kk[49][32];
    __shared__ float vv[49][32];
    __shared__ float S [49][56];
    __shared__ int   cnt[49];

    int tid = threadIdx.x;

    for (int idx = tid; idx < 49 * 32; idx += 256) {
        int n = idx >> 5, d = idx & 31;
        size_t base = (size_t)(win * 49 + n) * 1152 + head * 32 + d;
        q [n][d] = qkv[base]       * ATT_SCALE;
        kk[n][d] = qkv[base + 384];
        vv[n][d] = qkv[base + 768];
    }
    if (tid < 49) {
        int wi = win & 63;
        int wh = wi >> 3, ww = wi & 7;
        int i = tid / 7, j = tid % 7;
        int h = wh * 7 + i, w = ww * 7 + j;
        int rh = (h < HH - WSZ)   ? 0 : (h < HH - SHIFT   ? 1 : 2);
        int rw = (w < WWID - WSZ) ? 0 : (w < WWID - SHIFT ? 1 : 2);
        cnt[tid] = rh * 3 + rw;
    }
    __syncthreads();

    for (int p = tid; p < 49 * 49; p += 256) {
        int n = p / 49, m = p % 49;
        float acc = 0.f;
        #pragma unroll
        for (int d = 0; d < 32; d++) acc = fmaf(q[n][d], kk[m][d], acc);
        int di = n / 7 - m / 7 + 6;
        int dj = n % 7 - m % 7 + 6;
        float bias = relt[(di * 13 + dj) * NHEAD + head];
        float mask = (cnt[n] != cnt[m]) ? -100.f : 0.f;
        S[n][m] = acc + bias + mask;
    }
    __syncthreads();

    int wid = tid >> 5, lane = tid & 31;
    for (int n = wid; n < 49; n += 8) {
        float v0 = S[n][lane];
        float v1 = (lane < 17) ? S[n][lane + 32] : -1e30f;
        float mx = fmaxf(v0, v1);
        #pragma unroll
        for (int off = 16; off; off >>= 1)
            mx = fmaxf(mx, __shfl_xor_sync(~0u, mx, off));
        float e0 = expf(v0 - mx);
        float e1 = (lane < 17) ? expf(v1 - mx) : 0.f;
        float sm = e0 + e1;
        #pragma unroll
        for (int off = 16; off; off >>= 1)
            sm += __shfl_xor_sync(~0u, sm, off);
        float inv = 1.f / sm;
        S[n][lane] = e0 * inv;
        if (lane < 17) S[n][lane + 32] = e1 * inv;
    }
    __syncthreads();

    for (int idx = tid; idx < 49 * 32; idx += 256) {
        int n = idx >> 5, d = idx & 31;
        float acc = 0.f;
        #pragma unroll
        for (int m = 0; m < 49; m++) acc = fmaf(S[n][m], vv[m][d], acc);
        outp[(size_t)(win * 49 + n) * 384 + head * 32 + d] = acc;
    }
}

// ---------------------------------------------------------------------------
// Launch
// ---------------------------------------------------------------------------
extern "C" void kernel_launch(void* const* d_in, const int* in_sizes, int n_in,
                              void* d_out, int out_size)
{
    const float* x      = (const float*)d_in[0];
    const float* ln1_g  = (const float*)d_in[1];
    const float* ln1_b  = (const float*)d_in[2];
    const float* ln2_g  = (const float*)d_in[3];
    const float* ln2_b  = (const float*)d_in[4];
    const float* qkv_w  = (const float*)d_in[5];
    const float* qkv_b  = (const float*)d_in[6];
    const float* proj_w = (const float*)d_in[7];
    const float* proj_b = (const float*)d_in[8];
    const float* mlp_w1 = (const float*)d_in[9];
    const float* mlp_b1 = (const float*)d_in[10];
    const float* mlp_w2 = (const float*)d_in[11];
    const float* mlp_b2 = (const float*)d_in[12];
    const float* relt   = (const float*)d_in[13];
    float* out = (float*)d_out;

    float *wins, *qkvb, *att, *x1, *ln2o, *hbuf;
    cudaGetSymbolAddress((void**)&wins, g_wins);
    cudaGetSymbolAddress((void**)&qkvb, g_qkv);
    cudaGetSymbolAddress((void**)&att,  g_att);
    cudaGetSymbolAddress((void**)&x1,   g_x1);
    cudaGetSymbolAddress((void**)&ln2o, g_ln2);
    cudaGetSymbolAddress((void**)&hbuf, g_h);

    // 1. LN1 + cyclic shift + window partition
    ln_kernel<<<TOK, 384>>>(x, ln1_g, ln1_b, wins, 1);

    // 2. QKV GEMM: [50176,384] @ [384,1152]
    gemm_tc<0><<<dim3(1152 / 128, TOK / 128), 256>>>(
        wins, qkv_w, qkv_b, nullptr, qkvb, TOK, 1152, 384);

    // 3. Windowed attention
    attn_kernel<<<NWIN * NHEAD, 256>>>(qkvb, relt, att);

    // 4. Proj GEMM + window reverse + reverse roll + residual
    gemm_tc<2><<<dim3(384 / 128, TOK / 128), 256>>>(
        att, proj_w, proj_b, x, x1, TOK, 384, 384);

    // 5. LN2
    ln_kernel<<<TOK, 384>>>(x1, ln2_g, ln2_b, ln2o, 0);

    // 6. MLP1 + exact GELU: [50176,384] @ [384,1536]
    gemm_tc<1><<<dim3(1536 / 128, TOK / 128), 256>>>(
        ln2o, mlp_w1, mlp_b1, nullptr, hbuf, TOK, 1536, 384);

    // 7. MLP2 + residual: [50176,1536] @ [1536,384] -> d_out
    gemm_tc<3><<<dim3(384 / 128, TOK / 128), 256>>>(
        hbuf, mlp_w2, mlp_b2, x1, out, TOK, 384, 1536);
}

// round 3
// speedup vs baseline: 2.0111x; 1.7292x over previous
#include <cuda_runtime.h>
#include <math.h>

// ---------------------------------------------------------------------------
// Problem constants
// ---------------------------------------------------------------------------
constexpr int BATCH = 16;
constexpr int HH    = 56;
constexpr int WWID  = 56;
constexpr int CDIM  = 384;
constexpr int NHEAD = 12;
constexpr int WSZ   = 7;
constexpr int SHIFT = 3;
constexpr int NTOK  = 49;
constexpr int NWIN  = BATCH * 64;
constexpr int TOK   = NWIN * NTOK;        // 50176
constexpr float ATT_SCALE = 0.17677669529663687f;
constexpr float LN_EPS    = 1e-3f;

// ---------------------------------------------------------------------------
// Scratch
// ---------------------------------------------------------------------------
__device__ float g_wins[TOK * CDIM];
__device__ float g_qkv [TOK * 3 * CDIM];
__device__ float g_att [TOK * CDIM];
__device__ float g_x1  [TOK * CDIM];
__device__ float g_ln2 [TOK * CDIM];
__device__ float g_h   [TOK * 4 * CDIM];

// ---------------------------------------------------------------------------
// LayerNorm (one block per token). gather=1 fuses roll(-3,+3)+window partition
// ---------------------------------------------------------------------------
__global__ void __launch_bounds__(384)
ln_kernel(const float* __restrict__ X, const float* __restrict__ gam,
          const float* __restrict__ bet, float* __restrict__ Y, int gather)
{
    int tok = blockIdx.x;
    int src = tok;
    if (gather) {
        int win = tok / NTOK, n = tok % NTOK;
        int b  = win >> 6, wi = win & 63;
        int wh = wi >> 3,  ww = wi & 7;
        int i  = n / WSZ,  j  = n % WSZ;
        int hs = wh * WSZ + i, ws = ww * WSZ + j;
        int sh = hs + SHIFT; if (sh >= HH)  sh -= HH;
        int sw = ws - SHIFT; if (sw < 0)    sw += WWID;
        src = (b * HH + sh) * WWID + sw;
    }
    int c = threadIdx.x;
    float v = X[(size_t)src * CDIM + c];

    float a = v, b2 = v * v;
    #pragma unroll
    for (int off = 16; off; off >>= 1) {
        a  += __shfl_xor_sync(~0u, a,  off);
        b2 += __shfl_xor_sync(~0u, b2, off);
    }
    __shared__ float s1[12], s2[12];
    __shared__ float mu_s, rs_s;
    int wid = threadIdx.x >> 5, lane = threadIdx.x & 31;
    if (!lane) { s1[wid] = a; s2[wid] = b2; }
    __syncthreads();
    if (threadIdx.x == 0) {
        float sa = 0.f, sb = 0.f;
        #pragma unroll
        for (int k = 0; k < 12; k++) { sa += s1[k]; sb += s2[k]; }
        float mu  = sa / CDIM;
        float var = sb / CDIM - mu * mu;
        mu_s = mu;
        rs_s = rsqrtf(var + LN_EPS);
    }
    __syncthreads();
    Y[(size_t)tok * CDIM + c] = (v - mu_s) * rs_s * gam[c] + bet[c];
}

__device__ __forceinline__ int dest_row(int tok)
{
    int win = tok / NTOK, n = tok % NTOK;
    int b  = win >> 6, wi = win & 63;
    int wh = wi >> 3,  ww = wi & 7;
    int i  = n / WSZ,  j  = n % WSZ;
    int hs = wh * WSZ + i, ws = ww * WSZ + j;
    int h = hs + SHIFT; if (h >= HH)   h -= HH;
    int w = ws + SHIFT; if (w >= WWID) w -= WWID;
    return (b * HH + h) * WWID + w;
}

// ---------------------------------------------------------------------------
// tf32 tensor-core GEMM. 128x128 CTA tile, BK=16, 8 warps (64x32 warp tile),
// mma.sync.m16n8k8.tf32, fp32 accumulation.
// Producer: fragment-direct global gather (LDG.32, sector-coalesced) +
// conflict-free STS.128/STS.64. Consumer: LDS.128 (A) / LDS.64 (B).
// MODE 0: +bias  MODE 1: +bias,GELU  MODE 2: +bias,scatter+res  MODE 3: +bias,+res
// Requires M%128==0, N%128==0, K%16==0.
// ---------------------------------------------------------------------------
__device__ __forceinline__ unsigned f2tf(float v)
{
    unsigned r;
    asm("cvt.rna.tf32.f32 %0, %1;" : "=r"(r) : "f"(v));
    return r;
}

__device__ __forceinline__ void mma_tf32(float* c, const unsigned* a, const unsigned* b)
{
    asm volatile(
        "mma.sync.aligned.m16n8k8.row.col.f32.tf32.tf32.f32 "
        "{%0,%1,%2,%3}, {%4,%5,%6,%7}, {%8,%9}, {%0,%1,%2,%3};"
        : "+f"(c[0]), "+f"(c[1]), "+f"(c[2]), "+f"(c[3])
        : "r"(a[0]), "r"(a[1]), "r"(a[2]), "r"(a[3]), "r"(b[0]), "r"(b[1]));
}

template<int MODE>
__global__ void __launch_bounds__(256)
gemm_tc(const float* __restrict__ A, const float* __restrict__ B,
        const float* __restrict__ bias, const float* __restrict__ res,
        float* __restrict__ C, int M, int N, int K)
{
    __shared__ __align__(16) unsigned As[2][2048];   // 512 uint4 slots
    __shared__ __align__(16) unsigned Bs[2][2048];   // 1024 uint2 slots

    const int tid  = threadIdx.x;
    const int bm   = blockIdx.y * 128, bn = blockIdx.x * 128;
    const int warp = tid >> 5, lane = tid & 31;
    const int wm   = warp & 1, wn = warp >> 1;       // 2 x 4 warp grid

    // -------- producer constants --------
    // A slots: tid (ks=0) and tid+256 (ks=1); rows r0=bm+warp*16+(lane>>2), r1=r0+8;
    //          cols kt + (lane&3) + {0,4,8,12}
    // B slots: tid+256*it (it=0..3); col nb0=bn+warp*8+(lane>>2) (it even), nb0+64 (odd);
    //          rows kt + (lane&3) + {0,4} (it<2) or {8,12} (it>=2)
    const int pg = lane >> 2, pt = lane & 3;
    const float* Ap0 = A + (size_t)(bm + warp * 16 + pg) * K + pt;
    const float* Ap1 = Ap0 + (size_t)8 * K;
    const float* Bp  = B + (size_t)pt * N + bn + warp * 8 + pg;

    float av[8], bv[8];

    #define LOAD_GLB(KT)                                                     \
    {                                                                        \
        const float* a0p = Ap0 + (KT); const float* a1p = Ap1 + (KT);        \
        av[0] = a0p[0];  av[1] = a1p[0];  av[2] = a0p[4];  av[3] = a1p[4];   \
        av[4] = a0p[8];  av[5] = a1p[8];  av[6] = a0p[12]; av[7] = a1p[12];  \
        const float* bp = Bp + (size_t)(KT) * N;                             \
        bv[0] = bp[0];                 bv[1] = bp[(size_t)4 * N];            \
        bv[2] = bp[64];                bv[3] = bp[(size_t)4 * N + 64];       \
        bv[4] = bp[(size_t)8 * N];     bv[5] = bp[(size_t)12 * N];           \
        bv[6] = bp[(size_t)8 * N + 64];bv[7] = bp[(size_t)12 * N + 64];     \
    }

    #define STORE_SMEM(BUF)                                                  \
    {                                                                        \
        *(uint4*)&As[BUF][4 * tid] =                                         \
            make_uint4(f2tf(av[0]), f2tf(av[1]), f2tf(av[2]), f2tf(av[3]));  \
        *(uint4*)&As[BUF][4 * (tid + 256)] =                                 \
            make_uint4(f2tf(av[4]), f2tf(av[5]), f2tf(av[6]), f2tf(av[7]));  \
        *(uint2*)&Bs[BUF][2 * tid]         = make_uint2(f2tf(bv[0]), f2tf(bv[1])); \
        *(uint2*)&Bs[BUF][2 * (tid + 256)] = make_uint2(f2tf(bv[2]), f2tf(bv[3])); \
        *(uint2*)&Bs[BUF][2 * (tid + 512)] = make_uint2(f2tf(bv[4]), f2tf(bv[5])); \
        *(uint2*)&Bs[BUF][2 * (tid + 768)] = make_uint2(f2tf(bv[6]), f2tf(bv[7])); \
    }

    float acc[16][4];
    #pragma unroll
    for (int i = 0; i < 16; i++)
        #pragma unroll
        for (int j = 0; j < 4; j++) acc[i][j] = 0.f;

    LOAD_GLB(0)
    STORE_SMEM(0)
    int buf = 0;

    for (int kt = 16; ; kt += 16) {
        __syncthreads();
        bool more = kt < K;
        if (more) LOAD_GLB(kt)
        #pragma unroll
        for (int ks = 0; ks < 2; ks++) {
            unsigned afr[4][4], bfr[4][2];
            #pragma unroll
            for (int i = 0; i < 4; i++) {
                uint4 t = *(const uint4*)&As[buf][(((ks * 8) + (wm * 4 + i)) * 32 + lane) * 4];
                afr[i][0] = t.x; afr[i][1] = t.y; afr[i][2] = t.z; afr[i][3] = t.w;
            }
            #pragma unroll
            for (int j = 0; j < 4; j++) {
                uint2 t = *(const uint2*)&Bs[buf][(((ks * 16) + (wn * 4 + j)) * 32 + lane) * 2];
                bfr[j][0] = t.x; bfr[j][1] = t.y;
            }
            #pragma unroll
            for (int i = 0; i < 4; i++)
                #pragma unroll
                for (int j = 0; j < 4; j++)
                    mma_tf32(acc[i * 4 + j], afr[i], bfr[j]);
        }
        if (!more) break;
        STORE_SMEM(buf ^ 1)
        buf ^= 1;
    }
    #undef LOAD_GLB
    #undef STORE_SMEM

    // ---- epilogue ----
    const int g = lane >> 2, t = lane & 3;
    #pragma unroll
    for (int i = 0; i < 4; i++) {
        int r0 = bm + wm * 64 + i * 16 + g;
        int r1 = r0 + 8;
        int d0 = (MODE == 2) ? dest_row(r0) : r0;
        int d1 = (MODE == 2) ? dest_row(r1) : r1;
        #pragma unroll
        for (int j = 0; j < 4; j++) {
            int col = bn + wn * 32 + j * 8 + t * 2;
            float bc0 = bias[col], bc1 = bias[col + 1];
            float v00 = acc[i * 4 + j][0] + bc0;
            float v01 = acc[i * 4 + j][1] + bc1;
            float v10 = acc[i * 4 + j][2] + bc0;
            float v11 = acc[i * 4 + j][3] + bc1;
            if (MODE == 1) {
                v00 = 0.5f * v00 * (1.0f + erff(v00 * 0.70710678118654752f));
                v01 = 0.5f * v01 * (1.0f + erff(v01 * 0.70710678118654752f));
                v10 = 0.5f * v10 * (1.0f + erff(v10 * 0.70710678118654752f));
                v11 = 0.5f * v11 * (1.0f + erff(v11 * 0.70710678118654752f));
            }
            if (MODE == 2 || MODE == 3) {
                v00 += res[(size_t)d0 * N + col];
                v01 += res[(size_t)d0 * N + col + 1];
                v10 += res[(size_t)d1 * N + col];
                v11 += res[(size_t)d1 * N + col + 1];
            }
            *(float2*)&C[(size_t)d0 * N + col] = make_float2(v00, v01);
            *(float2*)&C[(size_t)d1 * N + col] = make_float2(v10, v11);
        }
    }
}

// ---------------------------------------------------------------------------
// Attention: one CTA per (window, head)
// ---------------------------------------------------------------------------
__global__ void __launch_bounds__(256)
attn_kernel(const float* __restrict__ qkv, const float* __restrict__ relt,
            float* __restrict__ outp)
{
    int blk  = blockIdx.x;
    int win  = blk / NHEAD;
    int head = blk % NHEAD;

    __shared__ float q [49][32];
    __shared__ float kk[49][32];
    __shared__ float vv[49][32];
    __shared__ float S [49][56];
    __shared__ int   cnt[49];

    int tid = threadIdx.x;

    for (int idx = tid; idx < 49 * 32; idx += 256) {
        int n = idx >> 5, d = idx & 31;
        size_t base = (size_t)(win * 49 + n) * 1152 + head * 32 + d;
        q [n][d] = qkv[base]       * ATT_SCALE;
        kk[n][d] = qkv[base + 384];
        vv[n][d] = qkv[base + 768];
    }
    if (tid < 49) {
        int wi = win & 63;
        int wh = wi >> 3, ww = wi & 7;
        int i = tid / 7, j = tid % 7;
        int h = wh * 7 + i, w = ww * 7 + j;
        int rh = (h < HH - WSZ)   ? 0 : (h < HH - SHIFT   ? 1 : 2);
        int rw = (w < WWID - WSZ) ? 0 : (w < WWID - SHIFT ? 1 : 2);
        cnt[tid] = rh * 3 + rw;
    }
    __syncthreads();

    for (int p = tid; p < 49 * 49; p += 256) {
        int n = p / 49, m = p % 49;
        float acc = 0.f;
        #pragma unroll
        for (int d = 0; d < 32; d++) acc = fmaf(q[n][d], kk[m][d], acc);
        int di = n / 7 - m / 7 + 6;
        int dj = n % 7 - m % 7 + 6;
        float bias = relt[(di * 13 + dj) * NHEAD + head];
        float mask = (cnt[n] != cnt[m]) ? -100.f : 0.f;
        S[n][m] = acc + bias + mask;
    }
    __syncthreads();

    int wid = tid >> 5, lane = tid & 31;
    for (int n = wid; n < 49; n += 8) {
        float v0 = S[n][lane];
        float v1 = (lane < 17) ? S[n][lane + 32] : -1e30f;
        float mx = fmaxf(v0, v1);
        #pragma unroll
        for (int off = 16; off; off >>= 1)
            mx = fmaxf(mx, __shfl_xor_sync(~0u, mx, off));
        float e0 = expf(v0 - mx);
        float e1 = (lane < 17) ? expf(v1 - mx) : 0.f;
        float sm = e0 + e1;
        #pragma unroll
        for (int off = 16; off; off >>= 1)
            sm += __shfl_xor_sync(~0u, sm, off);
        float inv = 1.f / sm;
        S[n][lane] = e0 * inv;
        if (lane < 17) S[n][lane + 32] = e1 * inv;
    }
    __syncthreads();

    for (int idx = tid; idx < 49 * 32; idx += 256) {
        int n = idx >> 5, d = idx & 31;
        float acc = 0.f;
        #pragma unroll
        for (int m = 0; m < 49; m++) acc = fmaf(S[n][m], vv[m][d], acc);
        outp[(size_t)(win * 49 + n) * 384 + head * 32 + d] = acc;
    }
}

// ---------------------------------------------------------------------------
// Launch
// ---------------------------------------------------------------------------
extern "C" void kernel_launch(void* const* d_in, const int* in_sizes, int n_in,
                              void* d_out, int out_size)
{
    const float* x      = (const float*)d_in[0];
    const float* ln1_g  = (const float*)d_in[1];
    const float* ln1_b  = (const float*)d_in[2];
    const float* ln2_g  = (const float*)d_in[3];
    const float* ln2_b  = (const float*)d_in[4];
    const float* qkv_w  = (const float*)d_in[5];
    const float* qkv_b  = (const float*)d_in[6];
    const float* proj_w = (const float*)d_in[7];
    const float* proj_b = (const float*)d_in[8];
    const float* mlp_w1 = (const float*)d_in[9];
    const float* mlp_b1 = (const float*)d_in[10];
    const float* mlp_w2 = (const float*)d_in[11];
    const float* mlp_b2 = (const float*)d_in[12];
    const float* relt   = (const float*)d_in[13];
    float* out = (float*)d_out;

    float *wins, *qkvb, *att, *x1, *ln2o, *hbuf;
    cudaGetSymbolAddress((void**)&wins, g_wins);
    cudaGetSymbolAddress((void**)&qkvb, g_qkv);
    cudaGetSymbolAddress((void**)&att,  g_att);
    cudaGetSymbolAddress((void**)&x1,   g_x1);
    cudaGetSymbolAddress((void**)&ln2o, g_ln2);
    cudaGetSymbolAddress((void**)&hbuf, g_h);

    // 1. LN1 + cyclic shift + window partition
    ln_kernel<<<TOK, 384>>>(x, ln1_g, ln1_b, wins, 1);

    // 2. QKV GEMM: [50176,384] @ [384,1152]
    gemm_tc<0><<<dim3(1152 / 128, TOK / 128), 256>>>(
        wins, qkv_w, qkv_b, nullptr, qkvb, TOK, 1152, 384);

    // 3. Windowed attention
    attn_kernel<<<NWIN * NHEAD, 256>>>(qkvb, relt, att);

    // 4. Proj GEMM + window reverse + reverse roll + residual
    gemm_tc<2><<<dim3(384 / 128, TOK / 128), 256>>>(
        att, proj_w, proj_b, x, x1, TOK, 384, 384);

    // 5. LN2
    ln_kernel<<<TOK, 384>>>(x1, ln2_g, ln2_b, ln2o, 0);

    // 6. MLP1 + exact GELU: [50176,384] @ [384,1536]
    gemm_tc<1><<<dim3(1536 / 128, TOK / 128), 256>>>(
        ln2o, mlp_w1, mlp_b1, nullptr, hbuf, TOK, 1536, 384);

    // 7. MLP2 + residual: [50176,1536] @ [1536,384] -> d_out
    gemm_tc<3><<<dim3(384 / 128, TOK / 128), 256>>>(
        hbuf, mlp_w2, mlp_b2, x1, out, TOK, 384, 1536);
}

// round 4
// speedup vs baseline: 2.3422x; 1.1647x over previous
#include <cuda_runtime.h>
#include <math.h>

// ---------------------------------------------------------------------------
// Problem constants
// ---------------------------------------------------------------------------
constexpr int BATCH = 16;
constexpr int HH    = 56;
constexpr int WWID  = 56;
constexpr int CDIM  = 384;
constexpr int NHEAD = 12;
constexpr int WSZ   = 7;
constexpr int SHIFT = 3;
constexpr int NTOK  = 49;
constexpr int NWIN  = BATCH * 64;
constexpr int TOK   = NWIN * NTOK;        // 50176
constexpr float ATT_SCALE = 0.17677669529663687f;
constexpr float LN_EPS    = 1e-3f;

// ---------------------------------------------------------------------------
// Scratch
// ---------------------------------------------------------------------------
__device__ float g_wins[TOK * CDIM];
__device__ float g_qkv [TOK * 3 * CDIM];
__device__ float g_att [TOK * CDIM];
__device__ float g_x1  [TOK * CDIM];
__device__ float g_ln2 [TOK * CDIM];
__device__ float g_h   [TOK * 4 * CDIM];

// ---------------------------------------------------------------------------
// LayerNorm (one block per token). gather=1 fuses roll(-3,+3)+window partition
// ---------------------------------------------------------------------------
__global__ void __launch_bounds__(384)
ln_kernel(const float* __restrict__ X, const float* __restrict__ gam,
          const float* __restrict__ bet, float* __restrict__ Y, int gather)
{
    int tok = blockIdx.x;
    int src = tok;
    if (gather) {
        int win = tok / NTOK, n = tok % NTOK;
        int b  = win >> 6, wi = win & 63;
        int wh = wi >> 3,  ww = wi & 7;
        int i  = n / WSZ,  j  = n % WSZ;
        int hs = wh * WSZ + i, ws = ww * WSZ + j;
        int sh = hs + SHIFT; if (sh >= HH)  sh -= HH;
        int sw = ws - SHIFT; if (sw < 0)    sw += WWID;
        src = (b * HH + sh) * WWID + sw;
    }
    int c = threadIdx.x;
    float v = X[(size_t)src * CDIM + c];

    float a = v, b2 = v * v;
    #pragma unroll
    for (int off = 16; off; off >>= 1) {
        a  += __shfl_xor_sync(~0u, a,  off);
        b2 += __shfl_xor_sync(~0u, b2, off);
    }
    __shared__ float s1[12], s2[12];
    __shared__ float mu_s, rs_s;
    int wid = threadIdx.x >> 5, lane = threadIdx.x & 31;
    if (!lane) { s1[wid] = a; s2[wid] = b2; }
    __syncthreads();
    if (threadIdx.x == 0) {
        float sa = 0.f, sb = 0.f;
        #pragma unroll
        for (int k = 0; k < 12; k++) { sa += s1[k]; sb += s2[k]; }
        float mu  = sa / CDIM;
        float var = sb / CDIM - mu * mu;
        mu_s = mu;
        rs_s = rsqrtf(var + LN_EPS);
    }
    __syncthreads();
    Y[(size_t)tok * CDIM + c] = (v - mu_s) * rs_s * gam[c] + bet[c];
}

__device__ __forceinline__ int dest_row(int tok)
{
    int win = tok / NTOK, n = tok % NTOK;
    int b  = win >> 6, wi = win & 63;
    int wh = wi >> 3,  ww = wi & 7;
    int i  = n / WSZ,  j  = n % WSZ;
    int hs = wh * WSZ + i, ws = ww * WSZ + j;
    int h = hs + SHIFT; if (h >= HH)   h -= HH;
    int w = ws + SHIFT; if (w >= WWID) w -= WWID;
    return (b * HH + h) * WWID + w;
}

// ---------------------------------------------------------------------------
// tf32 tensor-core GEMM. 128x128 CTA tile, BK=16, 8 warps (64x32 warp tile),
// mma.sync.m16n8k8.tf32, fp32 accumulation.
// Producer: row-major LDG.128 + conflict-free swizzled STS.128 into
// fragment-slot layout. Consumer: 1-wavefront scalar LDS.32 per fragment reg.
// MODE 0: +bias  MODE 1: +bias,GELU  MODE 2: +bias,scatter+res  MODE 3: +bias,+res
// Requires M%128==0, N%128==0, K%16==0.
// ---------------------------------------------------------------------------
__device__ __forceinline__ unsigned f2tf(float v)
{
    unsigned r;
    asm("cvt.rna.tf32.f32 %0, %1;" : "=r"(r) : "f"(v));
    return r;
}

__device__ __forceinline__ void mma_tf32(float* c, const unsigned* a, const unsigned* b)
{
    asm volatile(
        "mma.sync.aligned.m16n8k8.row.col.f32.tf32.tf32.f32 "
        "{%0,%1,%2,%3}, {%4,%5,%6,%7}, {%8,%9}, {%0,%1,%2,%3};"
        : "+f"(c[0]), "+f"(c[1]), "+f"(c[2]), "+f"(c[3])
        : "r"(a[0]), "r"(a[1]), "r"(a[2]), "r"(a[3]), "r"(b[0]), "r"(b[1]));
}

// SMEM layout (words):
//  A word (m 0..127, c 0..15):
//    block = (ks*8 + m>>4)*4 + reg,  reg = ((m>>3)&1) + 2*((c>>2)&1), ks=c>>3
//    slot  = (((m&7) ^ (2*(c>>2))) * 4) + (c&3)       [group-XOR swizzle]
//    addr  = block*32 + slot
//  B word (k 0..15, n 0..127):
//    block = (ks*16 + n>>3)*2 + reg, reg = (k>>2)&1, ks=k>>3
//    slot  = ((k&3)*8 + (n&7)) ^ (((n>>3)&3) << 3)
//    addr  = block*32 + slot
template<int MODE>
__global__ void __launch_bounds__(256)
gemm_tc(const float* __restrict__ A, const float* __restrict__ B,
        const float* __restrict__ bias, const float* __restrict__ res,
        float* __restrict__ C, int M, int N, int K)
{
    __shared__ __align__(16) unsigned As[2][2048];
    __shared__ __align__(16) unsigned Bs[2][2048];

    const int tid  = threadIdx.x;
    const int bm   = blockIdx.y * 128, bn = blockIdx.x * 128;
    const int warp = tid >> 5, lane = tid & 31;
    const int wm   = warp & 1, wn = warp >> 1;       // 2 x 4 warp grid

    // -------- producer mapping --------
    // A: thread covers rows ma, ma+64; cols c0..c0+3 (one quad)
    const int ma = tid >> 2;
    const int qa = tid & 3;            // quad index = c>>2
    const float* Ap = A + (size_t)(bm + ma) * K + qa * 4;
    // store addr: block*32 + group*4 ; group = (ma&7) ^ (2*qa)
    const int aAddr = (((qa >> 1) * 8 + (ma >> 4)) * 4 + ((ma >> 3) & 1) + 2 * (qa & 1)) * 32
                    + (((ma & 7) ^ (2 * qa)) << 2);   // second row at +512

    // B: thread covers row kb; cols n0..n0+3 and n0+64..n0+67
    const int kb = tid >> 4;
    const int n0 = (tid & 15) << 2;
    const float* Bp = B + (size_t)kb * N + bn + n0;
    const int bAddr = (((kb >> 3) * 16 + (n0 >> 3)) * 2 + ((kb >> 2) & 1)) * 32
                    + ((((kb & 3) * 8) + (n0 & 7)) ^ (((n0 >> 3) & 3) << 3)); // +64 cols at +512

    float4 a0, a1, b0, b1;

    #define LOAD_GLB(KT)                                                     \
    {                                                                        \
        a0 = *(const float4*)(Ap + (KT));                                    \
        a1 = *(const float4*)(Ap + (size_t)64 * K + (KT));                   \
        b0 = *(const float4*)(Bp + (size_t)(KT) * N);                        \
        b1 = *(const float4*)(Bp + (size_t)(KT) * N + 64);                   \
    }

    #define STORE_SMEM(BUF)                                                  \
    {                                                                        \
        *(uint4*)&As[BUF][aAddr]       =                                     \
            make_uint4(f2tf(a0.x), f2tf(a0.y), f2tf(a0.z), f2tf(a0.w));      \
        *(uint4*)&As[BUF][aAddr + 512] =                                     \
            make_uint4(f2tf(a1.x), f2tf(a1.y), f2tf(a1.z), f2tf(a1.w));      \
        *(uint4*)&Bs[BUF][bAddr]       =                                     \
            make_uint4(f2tf(b0.x), f2tf(b0.y), f2tf(b0.z), f2tf(b0.w));      \
        *(uint4*)&Bs[BUF][bAddr + 512] =                                     \
            make_uint4(f2tf(b1.x), f2tf(b1.y), f2tf(b1.z), f2tf(b1.w));      \
    }

    float acc[16][4];
    #pragma unroll
    for (int i = 0; i < 16; i++)
        #pragma unroll
        for (int j = 0; j < 4; j++) acc[i][j] = 0.f;

    const int pbase = (lane & 3) * 8 + (lane >> 2);   // B consumer lane perm

    LOAD_GLB(0)
    STORE_SMEM(0)
    int buf = 0;

    for (int kt = 16; ; kt += 16) {
        __syncthreads();
        bool more = kt < K;
        if (more) LOAD_GLB(kt)
        #pragma unroll
        for (int ks = 0; ks < 2; ks++) {
            unsigned afr[4][4], bfr[4][2];
            #pragma unroll
            for (int i = 0; i < 4; i++) {
                int blk = ((ks * 8) + (wm * 4 + i)) * 4;
                #pragma unroll
                for (int r = 0; r < 4; r++) {
                    int q = 2 * ks + (r >> 1);
                    afr[i][r] = As[buf][(blk + r) * 32 + (lane ^ (q << 3))];
                }
            }
            #pragma unroll
            for (int j = 0; j < 4; j++) {
                int blk = ((ks * 16) + (wn * 4 + j)) * 2;
                int sl  = pbase ^ (j << 3);
                bfr[j][0] = Bs[buf][blk * 32 + sl];
                bfr[j][1] = Bs[buf][(blk + 1) * 32 + sl];
            }
            #pragma unroll
            for (int i = 0; i < 4; i++)
                #pragma unroll
                for (int j = 0; j < 4; j++)
                    mma_tf32(acc[i * 4 + j], afr[i], bfr[j]);
        }
        if (!more) break;
        STORE_SMEM(buf ^ 1)
        buf ^= 1;
    }
    #undef LOAD_GLB
    #undef STORE_SMEM

    // ---- epilogue ----
    const int g = lane >> 2, t = lane & 3;
    #pragma unroll
    for (int i = 0; i < 4; i++) {
        int r0 = bm + wm * 64 + i * 16 + g;
        int r1 = r0 + 8;
        int d0 = (MODE == 2) ? dest_row(r0) : r0;
        int d1 = (MODE == 2) ? dest_row(r1) : r1;
        #pragma unroll
        for (int j = 0; j < 4; j++) {
            int col = bn + wn * 32 + j * 8 + t * 2;
            float bc0 = bias[col], bc1 = bias[col + 1];
            float v00 = acc[i * 4 + j][0] + bc0;
            float v01 = acc[i * 4 + j][1] + bc1;
            float v10 = acc[i * 4 + j][2] + bc0;
            float v11 = acc[i * 4 + j][3] + bc1;
            if (MODE == 1) {
                v00 = 0.5f * v00 * (1.0f + erff(v00 * 0.70710678118654752f));
                v01 = 0.5f * v01 * (1.0f + erff(v01 * 0.70710678118654752f));
                v10 = 0.5f * v10 * (1.0f + erff(v10 * 0.70710678118654752f));
                v11 = 0.5f * v11 * (1.0f + erff(v11 * 0.70710678118654752f));
            }
            if (MODE == 2 || MODE == 3) {
                v00 += res[(size_t)d0 * N + col];
                v01 += res[(size_t)d0 * N + col + 1];
                v10 += res[(size_t)d1 * N + col];
                v11 += res[(size_t)d1 * N + col + 1];
            }
            *(float2*)&C[(size_t)d0 * N + col] = make_float2(v00, v01);
            *(float2*)&C[(size_t)d1 * N + col] = make_float2(v10, v11);
        }
    }
}

// ---------------------------------------------------------------------------
// Attention: one CTA per (window, head)
// ---------------------------------------------------------------------------
__global__ void __launch_bounds__(256)
attn_kernel(const float* __restrict__ qkv, const float* __restrict__ relt,
            float* __restrict__ outp)
{
    int blk  = blockIdx.x;
    int win  = blk / NHEAD;
    int head = blk % NHEAD;

    __shared__ float q [49][32];
    __shared__ float kk[49][32];
    __shared__ float vv[49][32];
    __shared__ float S [49][56];
    __shared__ int   cnt[49];

    int tid = threadIdx.x;

    for (int idx = tid; idx < 49 * 32; idx += 256) {
        int n = idx >> 5, d = idx & 31;
        size_t base = (size_t)(win * 49 + n) * 1152 + head * 32 + d;
        q [n][d] = qkv[base]       * ATT_SCALE;
        kk[n][d] = qkv[base + 384];
        vv[n][d] = qkv[base + 768];
    }
    if (tid < 49) {
        int wi = win & 63;
        int wh = wi >> 3, ww = wi & 7;
        int i = tid / 7, j = tid % 7;
        int h = wh * 7 + i, w = ww * 7 + j;
        int rh = (h < HH - WSZ)   ? 0 : (h < HH - SHIFT   ? 1 : 2);
        int rw = (w < WWID - WSZ) ? 0 : (w < WWID - SHIFT ? 1 : 2);
        cnt[tid] = rh * 3 + rw;
    }
    __syncthreads();

    for (int p = tid; p < 49 * 49; p += 256) {
        int n = p / 49, m = p % 49;
        float acc = 0.f;
        #pragma unroll
        for (int d = 0; d < 32; d++) acc = fmaf(q[n][d], kk[m][d], acc);
        int di = n / 7 - m / 7 + 6;
        int dj = n % 7 - m % 7 + 6;
        float bias = relt[(di * 13 + dj) * NHEAD + head];
        float mask = (cnt[n] != cnt[m]) ? -100.f : 0.f;
        S[n][m] = acc + bias + mask;
    }
    __syncthreads();

    int wid = tid >> 5, lane = tid & 31;
    for (int n = wid; n < 49; n += 8) {
        float v0 = S[n][lane];
        float v1 = (lane < 17) ? S[n][lane + 32] : -1e30f;
        float mx = fmaxf(v0, v1);
        #pragma unroll
        for (int off = 16; off; off >>= 1)
            mx = fmaxf(mx, __shfl_xor_sync(~0u, mx, off));
        float e0 = expf(v0 - mx);
        float e1 = (lane < 17) ? expf(v1 - mx) : 0.f;
        float sm = e0 + e1;
        #pragma unroll
        for (int off = 16; off; off >>= 1)
            sm += __shfl_xor_sync(~0u, sm, off);
        float inv = 1.f / sm;
        S[n][lane] = e0 * inv;
        if (lane < 17) S[n][lane + 32] = e1 * inv;
    }
    __syncthreads();

    for (int idx = tid; idx < 49 * 32; idx += 256) {
        int n = idx >> 5, d = idx & 31;
        float acc = 0.f;
        #pragma unroll
        for (int m = 0; m < 49; m++) acc = fmaf(S[n][m], vv[m][d], acc);
        outp[(size_t)(win * 49 + n) * 384 + head * 32 + d] = acc;
    }
}

// ---------------------------------------------------------------------------
// Launch
// ---------------------------------------------------------------------------
extern "C" void kernel_launch(void* const* d_in, const int* in_sizes, int n_in,
                              void* d_out, int out_size)
{
    const float* x      = (const float*)d_in[0];
    const float* ln1_g  = (const float*)d_in[1];
    const float* ln1_b  = (const float*)d_in[2];
    const float* ln2_g  = (const float*)d_in[3];
    const float* ln2_b  = (const float*)d_in[4];
    const float* qkv_w  = (const float*)d_in[5];
    const float* qkv_b  = (const float*)d_in[6];
    const float* proj_w = (const float*)d_in[7];
    const float* proj_b = (const float*)d_in[8];
    const float* mlp_w1 = (const float*)d_in[9];
    const float* mlp_b1 = (const float*)d_in[10];
    const float* mlp_w2 = (const float*)d_in[11];
    const float* mlp_b2 = (const float*)d_in[12];
    const float* relt   = (const float*)d_in[13];
    float* out = (float*)d_out;

    float *wins, *qkvb, *att, *x1, *ln2o, *hbuf;
    cudaGetSymbolAddress((void**)&wins, g_wins);
    cudaGetSymbolAddress((void**)&qkvb, g_qkv);
    cudaGetSymbolAddress((void**)&att,  g_att);
    cudaGetSymbolAddress((void**)&x1,   g_x1);
    cudaGetSymbolAddress((void**)&ln2o, g_ln2);
    cudaGetSymbolAddress((void**)&hbuf, g_h);

    // 1. LN1 + cyclic shift + window partition
    ln_kernel<<<TOK, 384>>>(x, ln1_g, ln1_b, wins, 1);

    // 2. QKV GEMM: [50176,384] @ [384,1152]
    gemm_tc<0><<<dim3(1152 / 128, TOK / 128), 256>>>(
        wins, qkv_w, qkv_b, nullptr, qkvb, TOK, 1152, 384);

    // 3. Windowed attention
    attn_kernel<<<NWIN * NHEAD, 256>>>(qkvb, relt, att);

    // 4. Proj GEMM + window reverse + reverse roll + residual
    gemm_tc<2><<<dim3(384 / 128, TOK / 128), 256>>>(
        att, proj_w, proj_b, x, x1, TOK, 384, 384);

    // 5. LN2
    ln_kernel<<<TOK, 384>>>(x1, ln2_g, ln2_b, ln2o, 0);

    // 6. MLP1 + exact GELU: [50176,384] @ [384,1536]
    gemm_tc<1><<<dim3(1536 / 128, TOK / 128), 256>>>(
        ln2o, mlp_w1, mlp_b1, nullptr, hbuf, TOK, 1536, 384);

    // 7. MLP2 + residual: [50176,1536] @ [1536,384] -> d_out
    gemm_tc<3><<<dim3(384 / 128, TOK / 128), 256>>>(
        hbuf, mlp_w2, mlp_b2, x1, out, TOK, 384, 1536);
}

// round 5
// speedup vs baseline: 2.6203x; 1.1187x over previous
#include <cuda_runtime.h>
#include <cuda_bf16.h>
#include <math.h>

// ---------------------------------------------------------------------------
// Problem constants
// ---------------------------------------------------------------------------
constexpr int BATCH = 16;
constexpr int HH    = 56;
constexpr int WWID  = 56;
constexpr int CDIM  = 384;
constexpr int NHEAD = 12;
constexpr int WSZ   = 7;
constexpr int SHIFT = 3;
constexpr int NTOK  = 49;
constexpr int NWIN  = BATCH * 64;
constexpr int TOK   = NWIN * NTOK;        // 50176
constexpr float ATT_SCALE = 0.17677669529663687f;
constexpr float LN_EPS    = 1e-3f;

// ---------------------------------------------------------------------------
// Scratch
// ---------------------------------------------------------------------------
__device__ float g_wins[TOK * CDIM];
__device__ float g_qkv [TOK * 3 * CDIM];
__device__ float g_att [TOK * CDIM];
__device__ float g_x1  [TOK * CDIM];
__device__ float g_ln2 [TOK * CDIM];
__device__ float g_h   [TOK * 4 * CDIM];

// ---------------------------------------------------------------------------
// LayerNorm (one block per token). gather=1 fuses roll(-3,+3)+window partition
// ---------------------------------------------------------------------------
__global__ void __launch_bounds__(384)
ln_kernel(const float* __restrict__ X, const float* __restrict__ gam,
          const float* __restrict__ bet, float* __restrict__ Y, int gather)
{
    int tok = blockIdx.x;
    int src = tok;
    if (gather) {
        int win = tok / NTOK, n = tok % NTOK;
        int b  = win >> 6, wi = win & 63;
        int wh = wi >> 3,  ww = wi & 7;
        int i  = n / WSZ,  j  = n % WSZ;
        int hs = wh * WSZ + i, ws = ww * WSZ + j;
        int sh = hs + SHIFT; if (sh >= HH)  sh -= HH;
        int sw = ws - SHIFT; if (sw < 0)    sw += WWID;
        src = (b * HH + sh) * WWID + sw;
    }
    int c = threadIdx.x;
    float v = X[(size_t)src * CDIM + c];

    float a = v, b2 = v * v;
    #pragma unroll
    for (int off = 16; off; off >>= 1) {
        a  += __shfl_xor_sync(~0u, a,  off);
        b2 += __shfl_xor_sync(~0u, b2, off);
    }
    __shared__ float s1[12], s2[12];
    __shared__ float mu_s, rs_s;
    int wid = threadIdx.x >> 5, lane = threadIdx.x & 31;
    if (!lane) { s1[wid] = a; s2[wid] = b2; }
    __syncthreads();
    if (threadIdx.x == 0) {
        float sa = 0.f, sb = 0.f;
        #pragma unroll
        for (int k = 0; k < 12; k++) { sa += s1[k]; sb += s2[k]; }
        float mu  = sa / CDIM;
        float var = sb / CDIM - mu * mu;
        mu_s = mu;
        rs_s = rsqrtf(var + LN_EPS);
    }
    __syncthreads();
    Y[(size_t)tok * CDIM + c] = (v - mu_s) * rs_s * gam[c] + bet[c];
}

__device__ __forceinline__ int dest_row(int tok)
{
    int win = tok / NTOK, n = tok % NTOK;
    int b  = win >> 6, wi = win & 63;
    int wh = wi >> 3,  ww = wi & 7;
    int i  = n / WSZ,  j  = n % WSZ;
    int hs = wh * WSZ + i, ws = ww * WSZ + j;
    int h = hs + SHIFT; if (h >= HH)   h -= HH;
    int w = ws + SHIFT; if (w >= WWID) w -= WWID;
    return (b * HH + h) * WWID + w;
}

// ---------------------------------------------------------------------------
// bf16 tensor-core GEMM. 128x128 CTA tile, BK=16, 8 warps (64x32 warp tile),
// mma.sync.m16n8k16.bf16, fp32 accumulation.
// SMEM holds k-pair-packed bf16x2 words in fragment-slot layout.
// Producer: 2x LDG.128 + 1x STS.128 per operand per thread, conflict-free.
// Consumer: 1-wavefront scalar LDS.32 per fragment reg (pure lane perms).
// MODE 0: +bias  MODE 1: +bias,GELU  MODE 2: +bias,scatter+res  MODE 3: +bias,+res
// Requires M%128==0, N%128==0, K%16==0.
// ---------------------------------------------------------------------------
__device__ __forceinline__ unsigned pack_bf2(float lo, float hi)
{
    __nv_bfloat162 h = __floats2bfloat162_rn(lo, hi);   // .x=lo (low 16 bits)
    return *(unsigned*)&h;
}

__device__ __forceinline__ void mma_bf16(float* c, const unsigned* a, const unsigned* b)
{
    asm volatile(
        "mma.sync.aligned.m16n8k16.row.col.f32.bf16.bf16.f32 "
        "{%0,%1,%2,%3}, {%4,%5,%6,%7}, {%8,%9}, {%0,%1,%2,%3};"
        : "+f"(c[0]), "+f"(c[1]), "+f"(c[2]), "+f"(c[3])
        : "r"(a[0]), "r"(a[1]), "r"(a[2]), "r"(a[3]), "r"(b[0]), "r"(b[1]));
}

// SMEM word layouts (1024 words per buffer):
//  A word (m 0..127, kp 0..7):  block = (m>>4)*4 + ((m>>3)&1) + 2*(kp>>2)
//                               slot  = ((m&7)*4 + (kp&3)) ^ ((kp>>2)<<4)
//  B word (kp 0..7, n 0..127):  block = (n>>3)*2 + (kp>>2)
//                               slot  = ((kp&3)*8 + (n&7)) ^ (((n>>3)&3)<<3)
template<int MODE>
__global__ void __launch_bounds__(256)
gemm_tc(const float* __restrict__ A, const float* __restrict__ B,
        const float* __restrict__ bias, const float* __restrict__ res,
        float* __restrict__ C, int M, int N, int K)
{
    __shared__ __align__(16) unsigned As[2][1024];
    __shared__ __align__(16) unsigned Bs[2][1024];

    const int tid  = threadIdx.x;
    const int bm   = blockIdx.y * 128, bn = blockIdx.x * 128;
    const int warp = tid >> 5, lane = tid & 31;
    const int wm   = warp & 1, wn = warp >> 1;       // 2 x 4 warp grid

    // -------- producer mapping --------
    // A: thread -> row ma = tid>>1, k-half h = tid&1 (cols h*8 .. h*8+7)
    const int ma = tid >> 1;
    const int ha = tid & 1;
    const float* Ap = A + (size_t)(bm + ma) * K + ha * 8;
    const int aAddr = ((ma >> 4) * 4 + ((ma >> 3) & 1) + 2 * ha) * 32
                    + (((ma & 7) * 4) ^ (ha << 4));

    // B: thread -> k-pair e = tid>>5 (rows 2e,2e+1), cols n0 = (tid&31)*4
    const int eb = tid >> 5;
    const int n0 = (tid & 31) << 2;
    const float* Bp = B + (size_t)(2 * eb) * N + bn + n0;
    const int bAddr = ((n0 >> 3) * 2 + (eb >> 2)) * 32
                    + ((((eb & 3) * 8) + (n0 & 7)) ^ (((n0 >> 3) & 3) << 3));

    float4 a0, a1, b0, b1;

    #define LOAD_GLB(KT)                                                     \
    {                                                                        \
        a0 = *(const float4*)(Ap + (KT));                                    \
        a1 = *(const float4*)(Ap + (KT) + 4);                                \
        b0 = *(const float4*)(Bp + (size_t)(KT) * N);                        \
        b1 = *(const float4*)(Bp + (size_t)((KT) + 1) * N);                  \
    }

    #define STORE_SMEM(BUF)                                                  \
    {                                                                        \
        *(uint4*)&As[BUF][aAddr] = make_uint4(                               \
            pack_bf2(a0.x, a0.y), pack_bf2(a0.z, a0.w),                      \
            pack_bf2(a1.x, a1.y), pack_bf2(a1.z, a1.w));                     \
        *(uint4*)&Bs[BUF][bAddr] = make_uint4(                               \
            pack_bf2(b0.x, b1.x), pack_bf2(b0.y, b1.y),                      \
            pack_bf2(b0.z, b1.z), pack_bf2(b0.w, b1.w));                     \
    }

    float acc[16][4];
    #pragma unroll
    for (int i = 0; i < 16; i++)
        #pragma unroll
        for (int j = 0; j < 4; j++) acc[i][j] = 0.f;

    const int pbase = (lane & 3) * 8 + (lane >> 2);   // B consumer lane perm

    LOAD_GLB(0)
    STORE_SMEM(0)
    int buf = 0;

    for (int kt = 16; ; kt += 16) {
        __syncthreads();
        bool more = kt < K;
        if (more) LOAD_GLB(kt)

        unsigned afr[4][4], bfr[4][2];
        #pragma unroll
        for (int i = 0; i < 4; i++) {
            int blk = (wm * 4 + i) * 4;
            afr[i][0] = As[buf][(blk + 0) * 32 + lane];
            afr[i][1] = As[buf][(blk + 1) * 32 + lane];
            afr[i][2] = As[buf][(blk + 2) * 32 + (lane ^ 16)];
            afr[i][3] = As[buf][(blk + 3) * 32 + (lane ^ 16)];
        }
        #pragma unroll
        for (int j = 0; j < 4; j++) {
            int blk = (wn * 4 + j) * 2;
            int sl  = pbase ^ (j << 3);
            bfr[j][0] = Bs[buf][blk * 32 + sl];
            bfr[j][1] = Bs[buf][(blk + 1) * 32 + sl];
        }
        #pragma unroll
        for (int i = 0; i < 4; i++)
            #pragma unroll
            for (int j = 0; j < 4; j++)
                mma_bf16(acc[i * 4 + j], afr[i], bfr[j]);

        if (!more) break;
        STORE_SMEM(buf ^ 1)
        buf ^= 1;
    }
    #undef LOAD_GLB
    #undef STORE_SMEM

    // ---- epilogue ----
    const int g = lane >> 2, t = lane & 3;
    #pragma unroll
    for (int i = 0; i < 4; i++) {
        int r0 = bm + wm * 64 + i * 16 + g;
        int r1 = r0 + 8;
        int d0 = (MODE == 2) ? dest_row(r0) : r0;
        int d1 = (MODE == 2) ? dest_row(r1) : r1;
        #pragma unroll
        for (int j = 0; j < 4; j++) {
            int col = bn + wn * 32 + j * 8 + t * 2;
            float bc0 = bias[col], bc1 = bias[col + 1];
            float v00 = acc[i * 4 + j][0] + bc0;
            float v01 = acc[i * 4 + j][1] + bc1;
            float v10 = acc[i * 4 + j][2] + bc0;
            float v11 = acc[i * 4 + j][3] + bc1;
            if (MODE == 1) {
                v00 = 0.5f * v00 * (1.0f + erff(v00 * 0.70710678118654752f));
                v01 = 0.5f * v01 * (1.0f + erff(v01 * 0.70710678118654752f));
                v10 = 0.5f * v10 * (1.0f + erff(v10 * 0.70710678118654752f));
                v11 = 0.5f * v11 * (1.0f + erff(v11 * 0.70710678118654752f));
            }
            if (MODE == 2 || MODE == 3) {
                v00 += res[(size_t)d0 * N + col];
                v01 += res[(size_t)d0 * N + col + 1];
                v10 += res[(size_t)d1 * N + col];
                v11 += res[(size_t)d1 * N + col + 1];
            }
            *(float2*)&C[(size_t)d0 * N + col] = make_float2(v00, v01);
            *(float2*)&C[(size_t)d1 * N + col] = make_float2(v10, v11);
        }
    }
}

// ---------------------------------------------------------------------------
// Attention: one CTA per (window, head)
// ---------------------------------------------------------------------------
__global__ void __launch_bounds__(256)
attn_kernel(const float* __restrict__ qkv, const float* __restrict__ relt,
            float* __restrict__ outp)
{
    int blk  = blockIdx.x;
    int win  = blk / NHEAD;
    int head = blk % NHEAD;

    __shared__ float q [49][32];
    __shared__ float kk[49][32];
    __shared__ float vv[49][32];
    __shared__ float S [49][56];
    __shared__ int   cnt[49];

    int tid = threadIdx.x;

    for (int idx = tid; idx < 49 * 32; idx += 256) {
        int n = idx >> 5, d = idx & 31;
        size_t base = (size_t)(win * 49 + n) * 1152 + head * 32 + d;
        q [n][d] = qkv[base]       * ATT_SCALE;
        kk[n][d] = qkv[base + 384];
        vv[n][d] = qkv[base + 768];
    }
    if (tid < 49) {
        int wi = win & 63;
        int wh = wi >> 3, ww = wi & 7;
        int i = tid / 7, j = tid % 7;
        int h = wh * 7 + i, w = ww * 7 + j;
        int rh = (h < HH - WSZ)   ? 0 : (h < HH - SHIFT   ? 1 : 2);
        int rw = (w < WWID - WSZ) ? 0 : (w < WWID - SHIFT ? 1 : 2);
        cnt[tid] = rh * 3 + rw;
    }
    __syncthreads();

    for (int p = tid; p < 49 * 49; p += 256) {
        int n = p / 49, m = p % 49;
        float acc = 0.f;
        #pragma unroll
        for (int d = 0; d < 32; d++) acc = fmaf(q[n][d], kk[m][d], acc);
        int di = n / 7 - m / 7 + 6;
        int dj = n % 7 - m % 7 + 6;
        float bias = relt[(di * 13 + dj) * NHEAD + head];
        float mask = (cnt[n] != cnt[m]) ? -100.f : 0.f;
        S[n][m] = acc + bias + mask;
    }
    __syncthreads();

    int wid = tid >> 5, lane = tid & 31;
    for (int n = wid; n < 49; n += 8) {
        float v0 = S[n][lane];
        float v1 = (lane < 17) ? S[n][lane + 32] : -1e30f;
        float mx = fmaxf(v0, v1);
        #pragma unroll
        for (int off = 16; off; off >>= 1)
            mx = fmaxf(mx, __shfl_xor_sync(~0u, mx, off));
        float e0 = expf(v0 - mx);
        float e1 = (lane < 17) ? expf(v1 - mx) : 0.f;
        float sm = e0 + e1;
        #pragma unroll
        for (int off = 16; off; off >>= 1)
            sm += __shfl_xor_sync(~0u, sm, off);
        float inv = 1.f / sm;
        S[n][lane] = e0 * inv;
        if (lane < 17) S[n][lane + 32] = e1 * inv;
    }
    __syncthreads();

    for (int idx = tid; idx < 49 * 32; idx += 256) {
        int n = idx >> 5, d = idx & 31;
        float acc = 0.f;
        #pragma unroll
        for (int m = 0; m < 49; m++) acc = fmaf(S[n][m], vv[m][d], acc);
        outp[(size_t)(win * 49 + n) * 384 + head * 32 + d] = acc;
    }
}

// ---------------------------------------------------------------------------
// Launch
// ---------------------------------------------------------------------------
extern "C" void kernel_launch(void* const* d_in, const int* in_sizes, int n_in,
                              void* d_out, int out_size)
{
    const float* x      = (const float*)d_in[0];
    const float* ln1_g  = (const float*)d_in[1];
    const float* ln1_b  = (const float*)d_in[2];
    const float* ln2_g  = (const float*)d_in[3];
    const float* ln2_b  = (const float*)d_in[4];
    const float* qkv_w  = (const float*)d_in[5];
    const float* qkv_b  = (const float*)d_in[6];
    const float* proj_w = (const float*)d_in[7];
    const float* proj_b = (const float*)d_in[8];
    const float* mlp_w1 = (const float*)d_in[9];
    const float* mlp_b1 = (const float*)d_in[10];
    const float* mlp_w2 = (const float*)d_in[11];
    const float* mlp_b2 = (const float*)d_in[12];
    const float* relt   = (const float*)d_in[13];
    float* out = (float*)d_out;

    float *wins, *qkvb, *att, *x1, *ln2o, *hbuf;
    cudaGetSymbolAddress((void**)&wins, g_wins);
    cudaGetSymbolAddress((void**)&qkvb, g_qkv);
    cudaGetSymbolAddress((void**)&att,  g_att);
    cudaGetSymbolAddress((void**)&x1,   g_x1);
    cudaGetSymbolAddress((void**)&ln2o, g_ln2);
    cudaGetSymbolAddress((void**)&hbuf, g_h);

    // 1. LN1 + cyclic shift + window partition
    ln_kernel<<<TOK, 384>>>(x, ln1_g, ln1_b, wins, 1);

    // 2. QKV GEMM: [50176,384] @ [384,1152]
    gemm_tc<0><<<dim3(1152 / 128, TOK / 128), 256>>>(
        wins, qkv_w, qkv_b, nullptr, qkvb, TOK, 1152, 384);

    // 3. Windowed attention
    attn_kernel<<<NWIN * NHEAD, 256>>>(qkvb, relt, att);

    // 4. Proj GEMM + window reverse + reverse roll + residual
    gemm_tc<2><<<dim3(384 / 128, TOK / 128), 256>>>(
        att, proj_w, proj_b, x, x1, TOK, 384, 384);

    // 5. LN2
    ln_kernel<<<TOK, 384>>>(x1, ln2_g, ln2_b, ln2o, 0);

    // 6. MLP1 + exact GELU: [50176,384] @ [384,1536]
    gemm_tc<1><<<dim3(1536 / 128, TOK / 128), 256>>>(
        ln2o, mlp_w1, mlp_b1, nullptr, hbuf, TOK, 1536, 384);

    // 7. MLP2 + residual: [50176,1536] @ [1536,384] -> d_out
    gemm_tc<3><<<dim3(384 / 128, TOK / 128), 256>>>(
        hbuf, mlp_w2, mlp_b2, x1, out, TOK, 384, 1536);
}